// round 1
// baseline (speedup 1.0000x reference)
#include <cuda_runtime.h>
#include <cstdint>

// Problem constants
#define NTHREADS 256
#define TILE_B   16          // batch rows per block
#define NBLOCKS  (4096 / TILE_B)   // 256

// Shared-memory float offsets
#define OFF_W0P 0            // 64*8*16   = 8192
#define OFF_C0  8192         // 64*16     = 1024
#define OFF_W1  9216         // 8*128*16  = 16384
#define OFF_W2  25600        // 128*16    = 2048
#define OFF_W3  27648        // 128*16    = 2048
#define OFF_WF  29696        // 16
#define OFF_H0  29712        // 64 * 16 * 18 = 18432   [m][b][18] padded
#define OFF_H1  48144        // 16 * 130     = 2080    [b][130] padded
#define OFF_H2  50224        // 16 * 130     = 2080
#define OFF_HR  52304        // 16 * 16      = 256
#define SMEM_FLOATS 52560
#define SMEM_BYTES (SMEM_FLOATS * 4)   // 210240 B (opt-in > 48KB)

// Precomputed folded leaf weights: W0p[m,g,h] = Wg[m,g]*W0[m,g,h]; c0[m,h] = sum_g bg*W0
__device__ __align__(16) float g_W0p[512 * 8 * 16];
__device__ __align__(16) float g_c0[512 * 16];

using ull = unsigned long long;

__device__ __forceinline__ ull pack2(float x, float y) {
    ull r; asm("mov.b64 %0,{%1,%2};" : "=l"(r) : "f"(x), "f"(y)); return r;
}
__device__ __forceinline__ void fma2(ull& d, ull a, ull b) {
    asm("fma.rn.f32x2 %0,%1,%2,%3;" : "=l"(d) : "l"(a), "l"(b), "l"(d));
}
__device__ __forceinline__ float2 unpack2(ull v) {
    float2 r; asm("mov.b64 {%0,%1},%2;" : "=f"(r.x), "=f"(r.y) : "l"(v)); return r;
}
__device__ __forceinline__ float sigmoidf_(float v) {
    return __fdividef(1.0f, 1.0f + __expf(-v));
}

__device__ __forceinline__ void copy4(float* dst, const float* src, int n) {
    const float4* s4 = (const float4*)src;
    float4* d4 = (float4*)dst;
    for (int i = threadIdx.x; i < (n >> 2); i += NTHREADS) d4[i] = s4[i];
}

// ---------------------------------------------------------------------------
// Prep: fold Wg/bg into W0 -> W0p, c0
// ---------------------------------------------------------------------------
__global__ void prep_kernel(const float* __restrict__ Wg,
                            const float* __restrict__ bg,
                            const float* __restrict__ W0) {
    int i = blockIdx.x * blockDim.x + threadIdx.x;   // 0..8191
    if (i >= 512 * 16) return;
    int m = i >> 4, h = i & 15;
    float c = 0.f;
#pragma unroll
    for (int g = 0; g < 8; ++g) {
        float w = W0[(m * 8 + g) * 16 + h];
        g_W0p[m * 128 + g * 16 + h] = Wg[m * 8 + g] * w;
        c += bg[m * 8 + g] * w;
    }
    g_c0[i] = c;
}

// ---------------------------------------------------------------------------
// Fused DAG kernel: one block = 16 batch rows; loop over 8 root-subtrees.
// ---------------------------------------------------------------------------
extern __shared__ float smem[];

__global__ void __launch_bounds__(NTHREADS, 1)
fused_kernel(const float* __restrict__ x,
             const float* __restrict__ W1,
             const float* __restrict__ W2,
             const float* __restrict__ W3,
             const float* __restrict__ Wf,
             float* __restrict__ out) {
    float* sW0p = smem + OFF_W0P;
    float* sC0  = smem + OFF_C0;
    float* sW1  = smem + OFF_W1;
    float* sW2  = smem + OFF_W2;
    float* sW3  = smem + OFF_W3;
    float* sWf  = smem + OFF_WF;
    float* sH0  = smem + OFF_H0;   // [m_local 64][b 16][18]
    float* sH1  = smem + OFF_H1;   // [b 16][130]
    float* sH2  = smem + OFF_H2;   // [b 16][130]
    float* sHr  = smem + OFF_HR;   // [b 16][16]

    const int tid = threadIdx.x;
    const int b0  = blockIdx.x * TILE_B;

    // Root weights: load once
    copy4(sW3, W3, 2048);
    if (tid < 16) sWf[tid] = Wf[tid];

#pragma unroll 1
    for (int s2 = 0; s2 < 8; ++s2) {
        __syncthreads();   // prior subtree's consumers done before overwrite
        // Stage this subtree's weights into SMEM (L2 -> SMEM)
        copy4(sW0p, g_W0p + s2 * 8192, 8192);
        copy4(sC0,  g_c0  + s2 * 1024, 1024);
        copy4(sW1,  W1 + s2 * 16384, 16384);
        copy4(sW2,  W2 + s2 * 2048,  2048);
        __syncthreads();

        // ---- Level 0: 64 leaves x 16 rows; thread item = (b, m) ----
#pragma unroll
        for (int it = 0; it < 4; ++it) {
            int idx = tid + it * NTHREADS;       // 0..1023
            int b = idx & 15, m = idx >> 4;
            const float4* xr = (const float4*)x + (((size_t)(b0 + b)) << 10)
                               + ((s2 * 64 + m) << 1);
            float4 xa = xr[0], xb = xr[1];
            float xg[8] = {xa.x, xa.y, xa.z, xa.w, xb.x, xb.y, xb.z, xb.w};

            ull acc[8];
            const ull* c0p = (const ull*)(sC0 + m * 16);
#pragma unroll
            for (int p = 0; p < 8; ++p) acc[p] = c0p[p];

            const ull* wp = (const ull*)(sW0p + m * 128);
#pragma unroll
            for (int g = 0; g < 8; ++g) {
                ull ag = pack2(xg[g], xg[g]);
#pragma unroll
                for (int p = 0; p < 8; ++p) fma2(acc[p], ag, wp[g * 8 + p]);
            }
            float* o = sH0 + m * 288 + b * 18;
#pragma unroll
            for (int p = 0; p < 8; ++p) {
                float2 v = unpack2(acc[p]);
                float2 s; s.x = sigmoidf_(v.x); s.y = sigmoidf_(v.y);
                ((float2*)o)[p] = s;
            }
        }
        __syncthreads();

        // ---- Level 1: 8 modules (128->16); thread = (b, j, h-half) ----
        {
            int b  = tid & 15;
            int j  = (tid >> 4) & 7;
            int hh = tid >> 7;                         // 0 or 1
            const float* in = sH0 + (j * 8) * 288 + b * 18;
            const float* w  = sW1 + j * 2048 + hh * 8; // row k: stride 16 floats
            ull acc[4] = {0ull, 0ull, 0ull, 0ull};
#pragma unroll 1
            for (int c = 0; c < 8; ++c) {              // child leaf
                const float* inc = in + c * 288;
                const ull* wc = (const ull*)(w + c * 256);
#pragma unroll
                for (int h2 = 0; h2 < 8; ++h2) {       // k pairs within child
                    float2 a = *(const float2*)(inc + h2 * 2);
                    ull a0 = pack2(a.x, a.x);
                    ull a1 = pack2(a.y, a.y);
                    const ull* w0r = wc + (2 * h2) * 8;
                    const ull* w1r = wc + (2 * h2 + 1) * 8;
#pragma unroll
                    for (int p = 0; p < 4; ++p) fma2(acc[p], a0, w0r[p]);
#pragma unroll
                    for (int p = 0; p < 4; ++p) fma2(acc[p], a1, w1r[p]);
                }
            }
            float* o = sH1 + b * 130 + j * 16 + hh * 8;
#pragma unroll
            for (int p = 0; p < 4; ++p) {
                float2 v = unpack2(acc[p]);
                float2 s; s.x = sigmoidf_(v.x); s.y = sigmoidf_(v.y);
                ((float2*)o)[p] = s;
            }
        }
        __syncthreads();

        // ---- Level 2: 1 module (128->16); thread = (b, h-pair), 128 active ----
        if (tid < 128) {
            int b = tid & 15, hp = tid >> 4;           // hp 0..7
            const float* in = sH1 + b * 130;
            const float* w  = sW2 + hp * 2;
            ull acc = 0ull;
#pragma unroll 4
            for (int k = 0; k < 128; k += 2) {
                float2 a = *(const float2*)(in + k);
                ull a0 = pack2(a.x, a.x);
                ull a1 = pack2(a.y, a.y);
                ull w0 = *(const ull*)(w + k * 16);
                ull w1 = *(const ull*)(w + (k + 1) * 16);
                fma2(acc, a0, w0);
                fma2(acc, a1, w1);
            }
            float2 v = unpack2(acc);
            float2 s; s.x = sigmoidf_(v.x); s.y = sigmoidf_(v.y);
            *(float2*)(sH2 + b * 130 + s2 * 16 + hp * 2) = s;
        }
    }
    __syncthreads();

    // ---- Root: 128 -> 16, sigmoid, then dot with Wf ----
    {
        int b = tid & 15, h = tid >> 4;                // 256 threads
        const float* in = sH2 + b * 130;
        float acc = 0.f;
#pragma unroll 8
        for (int k = 0; k < 128; ++k) acc = fmaf(in[k], sW3[k * 16 + h], acc);
        sHr[b * 16 + h] = sigmoidf_(acc) * sWf[h];
    }
    __syncthreads();
    if (tid < 16) {
        const float* r = sHr + tid * 16;
        float acc = 0.f;
#pragma unroll
        for (int h = 0; h < 16; ++h) acc += r[h];
        out[b0 + tid] = acc;
    }
}

// ---------------------------------------------------------------------------
extern "C" void kernel_launch(void* const* d_in, const int* in_sizes, int n_in,
                              void* d_out, int out_size) {
    const float* x  = (const float*)d_in[0];
    const float* Wg = (const float*)d_in[1];
    const float* bg = (const float*)d_in[2];
    const float* W0 = (const float*)d_in[3];
    const float* W1 = (const float*)d_in[4];
    const float* W2 = (const float*)d_in[5];
    const float* W3 = (const float*)d_in[6];
    const float* Wf = (const float*)d_in[7];
    float* out = (float*)d_out;

    cudaFuncSetAttribute(fused_kernel,
                         cudaFuncAttributeMaxDynamicSharedMemorySize, SMEM_BYTES);

    prep_kernel<<<32, 256>>>(Wg, bg, W0);
    fused_kernel<<<NBLOCKS, NTHREADS, SMEM_BYTES>>>(x, W1, W2, W3, Wf, out);
}

// round 2
// speedup vs baseline: 1.2140x; 1.2140x over previous
#include <cuda_runtime.h>
#include <cstdint>

#define NTHREADS 256
#define TILE_B   16
#define NBLOCKS  (4096 / TILE_B)   // 256

// Shared-memory float offsets (padded layouts for bank-conflict avoidance)
#define OFF_W0P 0                      // 64 * 132 = 8448  (m-stride 132)
#define OFF_C0  8448                   // 64 * 24  = 1536  (m-stride 24)
#define OFF_W1  9984                   // 8*128*16 = 16384 (dense)
#define OFF_W2  26368                  // 128*16   = 2048
#define OFF_W3  28416                  // 128*16   = 2048
#define OFF_WF  30464                  // 16 (pad 32)
#define OFF_H0  30496                  // 64 * 324 (m-stride 324 = 16*20+4, b-stride 20)
#define OFF_H1  51232                  // 16 * 132
#define OFF_H2  53344                  // 16 * 132
#define OFF_HR  55456                  // 16 * 16
#define SMEM_FLOATS 55712
#define SMEM_BYTES (SMEM_FLOATS * 4)   // 222848 B

// Folded leaf weights: W0p[m,g,h] = Wg[m,g]*W0[m,g,h]; c0[m,h] = sum_g bg*W0
__device__ __align__(16) float g_W0p[512 * 128];
__device__ __align__(16) float g_c0[512 * 16];

using ull = unsigned long long;

__device__ __forceinline__ ull pack2(float x, float y) {
    ull r; asm("mov.b64 %0,{%1,%2};" : "=l"(r) : "f"(x), "f"(y)); return r;
}
__device__ __forceinline__ void fma2(ull& d, ull a, ull b) {
    asm("fma.rn.f32x2 %0,%1,%2,%3;" : "=l"(d) : "l"(a), "l"(b), "l"(d));
}
__device__ __forceinline__ float2 unpack2(ull v) {
    float2 r; asm("mov.b64 {%0,%1},%2;" : "=f"(r.x), "=f"(r.y) : "l"(v)); return r;
}
// sigmoid(x) = 0.5*tanh(0.5x) + 0.5  -> 1 MUFU.TANH + 1 FFMA
__device__ __forceinline__ float sigmoidf_(float v) {
    float t;
    asm("tanh.approx.f32 %0, %1;" : "=f"(t) : "f"(v * 0.5f));
    return fmaf(t, 0.5f, 0.5f);
}

__device__ __forceinline__ void copy4(float* dst, const float* src, int n) {
    const float4* s4 = (const float4*)src;
    float4* d4 = (float4*)dst;
    for (int i = threadIdx.x; i < (n >> 2); i += NTHREADS) d4[i] = s4[i];
}

// ---------------------------------------------------------------------------
__global__ void prep_kernel(const float* __restrict__ Wg,
                            const float* __restrict__ bg,
                            const float* __restrict__ W0) {
    int i = blockIdx.x * blockDim.x + threadIdx.x;   // 0..8191
    if (i >= 512 * 16) return;
    int m = i >> 4, h = i & 15;
    float c = 0.f;
#pragma unroll
    for (int g = 0; g < 8; ++g) {
        float w = W0[(m * 8 + g) * 16 + h];
        g_W0p[m * 128 + g * 16 + h] = Wg[m * 8 + g] * w;
        c += bg[m * 8 + g] * w;
    }
    g_c0[i] = c;
}

// ---------------------------------------------------------------------------
extern __shared__ float smem[];

__global__ void __launch_bounds__(NTHREADS, 1)
fused_kernel(const float* __restrict__ x,
             const float* __restrict__ W1,
             const float* __restrict__ W2,
             const float* __restrict__ W3,
             const float* __restrict__ Wf,
             float* __restrict__ out) {
    float* sW0p = smem + OFF_W0P;
    float* sC0  = smem + OFF_C0;
    float* sW1  = smem + OFF_W1;
    float* sW2  = smem + OFF_W2;
    float* sW3  = smem + OFF_W3;
    float* sWf  = smem + OFF_WF;
    float* sH0  = smem + OFF_H0;   // (m,b,h) at m*324 + b*20 + h
    float* sH1  = smem + OFF_H1;   // (b, j*16+h) at b*132 + ...
    float* sH2  = smem + OFF_H2;   // (b, s2*16+h) at b*132 + ...
    float* sHr  = smem + OFF_HR;

    const int tid = threadIdx.x;
    const int b0  = blockIdx.x * TILE_B;

    copy4(sW3, W3, 2048);
    if (tid < 16) sWf[tid] = Wf[tid];

#pragma unroll 1
    for (int s2 = 0; s2 < 8; ++s2) {
        __syncthreads();
        // ---- Stage subtree weights (with re-striding for bank layout) ----
        {
            const float4* src = (const float4*)(g_W0p + s2 * 8192);
            for (int i4 = tid; i4 < 2048; i4 += NTHREADS) {
                int m = i4 >> 5, r4 = i4 & 31;
                *(float4*)(sW0p + m * 132 + r4 * 4) = src[i4];
            }
            const float4* csrc = (const float4*)(g_c0 + s2 * 1024);
            for (int i4 = tid; i4 < 256; i4 += NTHREADS) {
                int m = i4 >> 2, r4 = i4 & 3;
                *(float4*)(sC0 + m * 24 + r4 * 4) = csrc[i4];
            }
            copy4(sW1, W1 + s2 * 16384, 16384);
            copy4(sW2, W2 + s2 * 2048, 2048);
        }
        __syncthreads();

        // ---- Level 0: thread = (bq = tid&3, m = tid>>2); 4 batch rows each ----
        {
            const int bq = tid & 3;
            const int m  = tid >> 2;           // 0..63
            float xs[4][8];
#pragma unroll
            for (int i = 0; i < 4; ++i) {
                const float4* xr = (const float4*)x
                    + (((size_t)(b0 + bq * 4 + i)) << 10) + ((s2 * 64 + m) << 1);
                float4 u = xr[0], v = xr[1];
                xs[i][0] = u.x; xs[i][1] = u.y; xs[i][2] = u.z; xs[i][3] = u.w;
                xs[i][4] = v.x; xs[i][5] = v.y; xs[i][6] = v.z; xs[i][7] = v.w;
            }
            ull acc[4][8];
            const ulonglong2* c0p = (const ulonglong2*)(sC0 + m * 24);
#pragma unroll
            for (int p = 0; p < 4; ++p) {
                ulonglong2 c = c0p[p];
#pragma unroll
                for (int i = 0; i < 4; ++i) { acc[i][2*p] = c.x; acc[i][2*p+1] = c.y; }
            }
            const ulonglong2* wp = (const ulonglong2*)(sW0p + m * 132);
#pragma unroll
            for (int g = 0; g < 8; ++g) {
                ulonglong2 wA = wp[g*4+0], wB = wp[g*4+1], wC = wp[g*4+2], wD = wp[g*4+3];
#pragma unroll
                for (int i = 0; i < 4; ++i) {
                    ull ag = pack2(xs[i][g], xs[i][g]);
                    fma2(acc[i][0], ag, wA.x); fma2(acc[i][1], ag, wA.y);
                    fma2(acc[i][2], ag, wB.x); fma2(acc[i][3], ag, wB.y);
                    fma2(acc[i][4], ag, wC.x); fma2(acc[i][5], ag, wC.y);
                    fma2(acc[i][6], ag, wD.x); fma2(acc[i][7], ag, wD.y);
                }
            }
#pragma unroll
            for (int i = 0; i < 4; ++i) {
                float* o = sH0 + m * 324 + (bq * 4 + i) * 20;
#pragma unroll
                for (int p = 0; p < 4; ++p) {
                    float2 v0 = unpack2(acc[i][2*p]);
                    float2 v1 = unpack2(acc[i][2*p+1]);
                    float4 t;
                    t.x = sigmoidf_(v0.x); t.y = sigmoidf_(v0.y);
                    t.z = sigmoidf_(v1.x); t.w = sigmoidf_(v1.y);
                    *(float4*)(o + p * 4) = t;
                }
            }
        }
        __syncthreads();

        // ---- Level 1: thread = (b = tid&15, hp = (tid>>4)&1, j = tid>>5); 8 h each ----
        {
            const int b  = tid & 15;
            const int hp = (tid >> 4) & 1;
            const int j  = tid >> 5;
            const float* aBase = sH0 + (j * 8) * 324 + b * 20;
            const float* wBase = sW1 + j * 2048 + hp * 8;
            ull acc[4] = {0ull, 0ull, 0ull, 0ull};
#pragma unroll 1
            for (int c = 0; c < 8; ++c) {
                const float* ac  = aBase + c * 324;
                const float* wcf = wBase + c * 256;
#pragma unroll
                for (int k4 = 0; k4 < 4; ++k4) {
                    float4 a4 = *(const float4*)(ac + k4 * 4);
                    float av[4] = {a4.x, a4.y, a4.z, a4.w};
                    const float* wk = wcf + k4 * 64;
#pragma unroll
                    for (int q = 0; q < 4; ++q) {
                        ull ad = pack2(av[q], av[q]);
                        const ulonglong2* w2 = (const ulonglong2*)(wk + q * 16);
                        ulonglong2 wA = w2[0];
                        ulonglong2 wB = w2[1];
                        fma2(acc[0], ad, wA.x); fma2(acc[1], ad, wA.y);
                        fma2(acc[2], ad, wB.x); fma2(acc[3], ad, wB.y);
                    }
                }
            }
            float* o = sH1 + b * 132 + j * 16 + hp * 8;
            float2 v0 = unpack2(acc[0]), v1 = unpack2(acc[1]);
            float2 v2 = unpack2(acc[2]), v3 = unpack2(acc[3]);
            float4 r0, r1;
            r0.x = sigmoidf_(v0.x); r0.y = sigmoidf_(v0.y);
            r0.z = sigmoidf_(v1.x); r0.w = sigmoidf_(v1.y);
            r1.x = sigmoidf_(v2.x); r1.y = sigmoidf_(v2.y);
            r1.z = sigmoidf_(v3.x); r1.w = sigmoidf_(v3.y);
            *(float4*)o = r0;
            *(float4*)(o + 4) = r1;
        }
        __syncthreads();

        // ---- Level 2: 128 threads, thread = (b, hp 0..7), 2 h each ----
        if (tid < 128) {
            const int b = tid & 15, hp = tid >> 4;
            const float* in = sH1 + b * 132;
            const float* w  = sW2 + hp * 2;
            ull acc = 0ull;
#pragma unroll
            for (int k4 = 0; k4 < 32; ++k4) {
                float4 a4 = *(const float4*)(in + k4 * 4);
                float av[4] = {a4.x, a4.y, a4.z, a4.w};
#pragma unroll
                for (int q = 0; q < 4; ++q) {
                    ull ad = pack2(av[q], av[q]);
                    ull wv = *(const ull*)(w + (k4 * 4 + q) * 16);
                    fma2(acc, ad, wv);
                }
            }
            float2 v = unpack2(acc);
            float2 s; s.x = sigmoidf_(v.x); s.y = sigmoidf_(v.y);
            *(float2*)(sH2 + b * 132 + s2 * 16 + hp * 2) = s;
        }
    }
    __syncthreads();

    // ---- Root: 128 -> 16, sigmoid, scale by Wf ----
    {
        const int b = tid & 15, h = tid >> 4;
        const float* in = sH2 + b * 132;
        float acc = 0.f;
#pragma unroll
        for (int k4 = 0; k4 < 32; ++k4) {
            float4 a4 = *(const float4*)(in + k4 * 4);
            acc = fmaf(a4.x, sW3[(k4 * 4 + 0) * 16 + h], acc);
            acc = fmaf(a4.y, sW3[(k4 * 4 + 1) * 16 + h], acc);
            acc = fmaf(a4.z, sW3[(k4 * 4 + 2) * 16 + h], acc);
            acc = fmaf(a4.w, sW3[(k4 * 4 + 3) * 16 + h], acc);
        }
        sHr[b * 16 + h] = sigmoidf_(acc) * sWf[h];
    }
    __syncthreads();
    if (tid < 16) {
        const float* r = sHr + tid * 16;
        float acc = 0.f;
#pragma unroll
        for (int h = 0; h < 16; ++h) acc += r[h];
        out[b0 + tid] = acc;
    }
}

// ---------------------------------------------------------------------------
extern "C" void kernel_launch(void* const* d_in, const int* in_sizes, int n_in,
                              void* d_out, int out_size) {
    const float* x  = (const float*)d_in[0];
    const float* Wg = (const float*)d_in[1];
    const float* bg = (const float*)d_in[2];
    const float* W0 = (const float*)d_in[3];
    const float* W1 = (const float*)d_in[4];
    const float* W2 = (const float*)d_in[5];
    const float* W3 = (const float*)d_in[6];
    const float* Wf = (const float*)d_in[7];
    float* out = (float*)d_out;

    cudaFuncSetAttribute(fused_kernel,
                         cudaFuncAttributeMaxDynamicSharedMemorySize, SMEM_BYTES);

    prep_kernel<<<32, 256>>>(Wg, bg, W0);
    fused_kernel<<<NBLOCKS, NTHREADS, SMEM_BYTES>>>(x, W1, W2, W3, Wf, out);
}